// round 14
// baseline (speedup 1.0000x reference)
#include <cuda_runtime.h>
#include <cuda_bf16.h>
#include <cstdint>

#define NN 50000
#define EE 800000
#define FMAX 512
#define NPAD 128   // extra rows: unpredicated cp.async of last row-block stays in-bounds

// Scratch (static device globals — allocation-free)
__device__ float g_X[(size_t)NN * FMAX];   // ping
__device__ float g_H[(size_t)NN * FMAX];   // pong
__device__ __nv_bfloat16 g_Ahi[(size_t)(NN + NPAD) * FMAX];
__device__ __nv_bfloat16 g_Alo[(size_t)(NN + NPAD) * FMAX];
__device__ __nv_bfloat16 g_Bhi[(size_t)(NN + NPAD) * FMAX];
__device__ __nv_bfloat16 g_Blo[(size_t)(NN + NPAD) * FMAX];
// per-layer transposed weight hi/lo
__device__ __nv_bfloat16 g_WT2h[64 * 256],  g_WT2l[64 * 256];
__device__ __nv_bfloat16 g_WT3h[256 * 512], g_WT3l[256 * 512];
__device__ __nv_bfloat16 g_WT4h[512 * 256], g_WT4l[512 * 256];
__device__ __nv_bfloat16 g_WT5h[256 * 64],  g_WT5l[256 * 64];
__device__ float g_dinv[NN];
__device__ int   g_cnt[NN];
__device__ int   g_rowptr[NN + 1];
__device__ int   g_cursor[NN];
__device__ int2  g_csr[EE];     // {src, __float_as_int(norm)}

// ---------------------------------------------------------------------------
// Host-side streams/events, created ONCE at program load (before the harness
// pre-capture memory baseline). kernel_launch creates/destroys nothing.
// ---------------------------------------------------------------------------
struct SideStreams {
    cudaStream_t sCsr = nullptr, sW = nullptr;
    cudaEvent_t evRoot = nullptr, evCsr = nullptr, evW = nullptr;
    SideStreams() {
        cudaStreamCreate(&sCsr);
        cudaStreamCreate(&sW);
        cudaEventCreateWithFlags(&evRoot, cudaEventDisableTiming);
        cudaEventCreateWithFlags(&evCsr,  cudaEventDisableTiming);
        cudaEventCreateWithFlags(&evW,    cudaEventDisableTiming);
        cudaEventRecord(evRoot, sCsr);
        cudaStreamWaitEvent(sW, evRoot, 0);
        cudaStreamSynchronize(sCsr);
        cudaStreamSynchronize(sW);
    }
};
static SideStreams g_ss;

__device__ __forceinline__ uint32_t smem_u32(const void* p) {
    uint32_t a;
    asm("{ .reg .u64 t; cvta.to.shared.u64 t, %1; cvt.u32.u64 %0, t; }"
        : "=r"(a) : "l"(p));
    return a;
}

// PDL: launch dependents early / wait for programmatic predecessor
#define PDL_TRIGGER() asm volatile("griddepcontrol.launch_dependents;" ::: "memory")
#define PDL_WAIT()    asm volatile("griddepcontrol.wait;" ::: "memory")

#define CP_ASYNC16(dst, src) \
    asm volatile("cp.async.cg.shared.global [%0], [%1], 16;" \
                 :: "r"(dst), "l"(src) : "memory")
#define CP_COMMIT() asm volatile("cp.async.commit_group;" ::: "memory")
#define CP_WAIT1()  asm volatile("cp.async.wait_group 1;" ::: "memory")
#define CP_WAIT0()  asm volatile("cp.async.wait_group 0;" ::: "memory")

// ===========================================================================
// CSR build + normalization (side stream — no PDL)
// ===========================================================================
__global__ void k_count(const int* __restrict__ dst) {
    int e = blockIdx.x * blockDim.x + threadIdx.x;
    if (e < EE) atomicAdd(&g_cnt[dst[e]], 1);
}

__global__ __launch_bounds__(1024) void k_scan() {
    __shared__ int sh[1024];
    int tid = threadIdx.x;
    const int chunk = (NN + 1023) / 1024;
    int base = tid * chunk;
    int sum = 0;
    for (int i = 0; i < chunk; i++) {
        int idx = base + i;
        if (idx < NN) sum += g_cnt[idx];
    }
    sh[tid] = sum;
    __syncthreads();
    for (int off = 1; off < 1024; off <<= 1) {
        int v = 0;
        if (tid >= off) v = sh[tid - off];
        __syncthreads();
        sh[tid] += v;
        __syncthreads();
    }
    int run = (tid > 0) ? sh[tid - 1] : 0;
    for (int i = 0; i < chunk; i++) {
        int idx = base + i;
        if (idx < NN) {
            g_rowptr[idx] = run;
            g_cursor[idx] = run;
            int c = g_cnt[idx];
            g_dinv[idx] = rsqrtf((float)(c + 1));
            run += c;
        }
    }
    if (tid == 0) g_rowptr[NN] = EE;
}

__global__ void k_fill(const int* __restrict__ src, const int* __restrict__ dst) {
    int e = blockIdx.x * blockDim.x + threadIdx.x;
    if (e < EE) {
        int s = src[e], d = dst[e];
        int pos = atomicAdd(&g_cursor[d], 1);
        int2 p;
        p.x = s;
        p.y = __float_as_int(g_dinv[s] * g_dinv[d]);
        g_csr[pos] = p;
    }
}

// ===========================================================================
// W[K][F] fp32 -> WT[F][K] bf16 hi/lo (transposed) (side stream — no PDL)
// ===========================================================================
__global__ void k_convW(const float* __restrict__ W,
                        __nv_bfloat16* __restrict__ WThi,
                        __nv_bfloat16* __restrict__ WTlo, int K, int F)
{
    int i = blockIdx.x * blockDim.x + threadIdx.x;
    if (i >= K * F) return;
    int k = i / F, f = i % F;
    float v = W[i];
    __nv_bfloat16 h = __float2bfloat16(v);
    WThi[(size_t)f * K + k] = h;
    WTlo[(size_t)f * K + k] = __float2bfloat16(v - __bfloat162float(h));
}

// ===========================================================================
// CSR aggregation (gather, no atomics); one float4 column per thread;
// packed int2 csr entries. Optional fp32 out and/or bf16 hi/lo split out.
// PDL: rowptr/dinv/bias loads pre-wait (written by event-gated ancestors);
// xin touched only after griddepcontrol.wait.
// ===========================================================================
__global__ __launch_bounds__(256) void k_agg(
    const float4* __restrict__ xin4, float4* __restrict__ out4,
    const float* __restrict__ bias, int F4, int do_relu,
    __nv_bfloat16* __restrict__ ohi, __nv_bfloat16* __restrict__ olo)
{
    long t = (long)blockIdx.x * blockDim.x + threadIdx.x;
    long total = (long)NN * F4;
    if (t >= total) { PDL_WAIT(); return; }
    int n = (int)(t / F4);
    int c = (int)(t % F4);

    // pre-wait preamble: CSR metadata + bias (independent of stream predecessor)
    float d = g_dinv[n];
    int s = g_rowptr[n];
    int e = g_rowptr[n + 1];
    float4 bv = make_float4(0.f, 0.f, 0.f, 0.f);
    if (bias) bv = ((const float4*)bias)[c];

    PDL_WAIT();   // predecessor (producer of xin) complete

    float w0 = d * d;
    float4 x = xin4[(size_t)n * F4 + c];
    float4 acc = make_float4(x.x * w0, x.y * w0, x.z * w0, x.w * w0);

    for (int j = s; j < e; j++) {
        int2 p = g_csr[j];
        float w = __int_as_float(p.y);
        float4 v = xin4[(size_t)p.x * F4 + c];
        acc.x += w * v.x;
        acc.y += w * v.y;
        acc.z += w * v.z;
        acc.w += w * v.w;
    }

    PDL_TRIGGER();   // successor may launch; it waits for our completion anyway

    acc.x += bv.x; acc.y += bv.y; acc.z += bv.z; acc.w += bv.w;
    if (do_relu) {
        acc.x = fmaxf(acc.x, 0.0f);
        acc.y = fmaxf(acc.y, 0.0f);
        acc.z = fmaxf(acc.z, 0.0f);
        acc.w = fmaxf(acc.w, 0.0f);
    }
    if (out4) out4[(size_t)n * F4 + c] = acc;
    if (ohi) {
        size_t base = (size_t)n * (F4 * 4) + (size_t)c * 4;
        float v[4] = {acc.x, acc.y, acc.z, acc.w};
#pragma unroll
        for (int q = 0; q < 2; q++) {
            __nv_bfloat16 h0 = __float2bfloat16(v[2 * q]);
            __nv_bfloat16 h1 = __float2bfloat16(v[2 * q + 1]);
            __nv_bfloat162 hh; hh.x = h0; hh.y = h1;
            __nv_bfloat162 ll;
            ll.x = __float2bfloat16(v[2 * q] - __bfloat162float(h0));
            ll.y = __float2bfloat16(v[2 * q + 1] - __bfloat162float(h1));
            *(__nv_bfloat162*)&ohi[base + 2 * q] = hh;
            *(__nv_bfloat162*)&olo[base + 2 * q] = ll;
        }
    }
}

// ===========================================================================
// Pipelined mma.sync bf16 3-split GEMM (2-stage double buffer).
// Requires K % 32 == 0. CTA tile 128 x BN, threads 2*BN, warp tile 64x32.
// D = Ah*Bh + Ah*Bl + Al*Bh (fp32 accum).
// Epilogue: fp32 C OR bf16 hi/lo split (bias/relu fused).
// PDL: wait before first load_stage; trigger after mainloop.
// ===========================================================================
#define KPAD 40   // smem row stride in bf16 (80B)

__device__ __forceinline__ void ldm_x4(uint32_t* r, uint32_t addr) {
    asm volatile("ldmatrix.sync.aligned.m8n8.x4.shared.b16 {%0,%1,%2,%3}, [%4];"
                 : "=r"(r[0]), "=r"(r[1]), "=r"(r[2]), "=r"(r[3]) : "r"(addr));
}

__device__ __forceinline__ void mma_bf16(float* c, const uint32_t* a,
                                         uint32_t b0, uint32_t b1) {
    asm volatile(
        "mma.sync.aligned.m16n8k16.row.col.f32.bf16.bf16.f32 "
        "{%0,%1,%2,%3}, {%4,%5,%6,%7}, {%8,%9}, {%0,%1,%2,%3};"
        : "+f"(c[0]), "+f"(c[1]), "+f"(c[2]), "+f"(c[3])
        : "r"(a[0]), "r"(a[1]), "r"(a[2]), "r"(a[3]), "r"(b0), "r"(b1));
}

template<int BN>
__device__ __forceinline__ void load_stage(
    uint32_t sbase, const __nv_bfloat16* Ah, const __nv_bfloat16* Al,
    const __nv_bfloat16* Bh, const __nv_bfloat16* Bl,
    int tid, int row0, int col0, int K, int k0)
{
    constexpr int NT = 2 * BN;
    constexpr int ST_AH = 0;
    constexpr int ST_AL = 128 * KPAD * 2;
    constexpr int ST_BH = 2 * 128 * KPAD * 2;
    constexpr int ST_BL = ST_BH + BN * KPAD * 2;

#pragma unroll
    for (int idx = tid; idx < 128 * 4; idx += NT) {
        int r = idx >> 2, q = idx & 3;
        size_t g = (size_t)(row0 + r) * K + k0 + q * 8;
        uint32_t so = (uint32_t)(r * (KPAD * 2) + q * 16);
        CP_ASYNC16(sbase + ST_AH + so, Ah + g);
        CP_ASYNC16(sbase + ST_AL + so, Al + g);
    }
#pragma unroll
    for (int idx = tid; idx < BN * 4; idx += NT) {
        int r = idx >> 2, q = idx & 3;
        size_t g = (size_t)(col0 + r) * K + k0 + q * 8;
        uint32_t so = (uint32_t)(r * (KPAD * 2) + q * 16);
        CP_ASYNC16(sbase + ST_BH + so, Bh + g);
        CP_ASYNC16(sbase + ST_BL + so, Bl + g);
    }
}

template<int BN>
__global__ __launch_bounds__(2 * BN) void k_mma_gemm(
    const __nv_bfloat16* __restrict__ Ah, const __nv_bfloat16* __restrict__ Al,
    const __nv_bfloat16* __restrict__ Bh, const __nv_bfloat16* __restrict__ Bl,
    float* __restrict__ C,
    __nv_bfloat16* __restrict__ ohi, __nv_bfloat16* __restrict__ olo,
    int M, int K, int F,
    const float* __restrict__ bias, int do_relu)
{
    constexpr int ST_AH = 0;
    constexpr int ST_AL = 128 * KPAD * 2;
    constexpr int ST_BH = 2 * 128 * KPAD * 2;
    constexpr int ST_BL = ST_BH + BN * KPAD * 2;
    constexpr int ST_BYTES = ST_BH + 2 * BN * KPAD * 2;

    extern __shared__ char smem[];
    const uint32_t sb = smem_u32(smem);
    const int tid  = threadIdx.x;
    const int lane = tid & 31;
    const int warp = tid >> 5;
    const int wm = warp & 1;
    const int wn = warp >> 1;
    const int row0 = blockIdx.y * 128;
    const int col0 = blockIdx.x * BN;

    float acc[4][4][4];
#pragma unroll
    for (int i = 0; i < 4; i++)
#pragma unroll
        for (int j = 0; j < 4; j++)
#pragma unroll
            for (int q = 0; q < 4; q++) acc[i][j][q] = 0.0f;

    const int nch = K / 32;

    PDL_WAIT();   // A (and possibly B) produced by programmatic predecessor

    load_stage<BN>(sb, Ah, Al, Bh, Bl, tid, row0, col0, K, 0);
    CP_COMMIT();

    for (int ch = 0; ch < nch; ch++) {
        if (ch + 1 < nch) {
            load_stage<BN>(sb + ((ch + 1) & 1) * ST_BYTES, Ah, Al, Bh, Bl,
                           tid, row0, col0, K, (ch + 1) * 32);
            CP_COMMIT();
            CP_WAIT1();
        } else {
            CP_WAIT0();
        }
        __syncthreads();

        const uint32_t st = sb + (ch & 1) * ST_BYTES;
        const uint32_t aAh = st + ST_AH;
        const uint32_t aAl = st + ST_AL;
        const uint32_t aBh = st + ST_BH;
        const uint32_t aBl = st + ST_BL;

#pragma unroll
        for (int ks = 0; ks < 32; ks += 16) {
            uint32_t fah[4][4], fal[4][4];
            const int qa = lane >> 3;
            const int arow_off = (lane & 7) + (qa & 1) * 8;
            const int akof = ks + (qa >> 1) * 8;
#pragma unroll
            for (int mt = 0; mt < 4; mt++) {
                int row = wm * 64 + mt * 16 + arow_off;
                uint32_t o = (uint32_t)(row * KPAD + akof) * 2;
                ldm_x4(fah[mt], aAh + o);
                ldm_x4(fal[mt], aAl + o);
            }
            uint32_t fbh[8], fbl[8];
            const int qb = lane >> 3;
            const int brow_base = (lane & 7) + (qb >> 1) * 8;
            const int bkof = ks + (qb & 1) * 8;
#pragma unroll
            for (int half = 0; half < 2; half++) {
                int rown = wn * 32 + half * 16 + brow_base;
                uint32_t o = (uint32_t)(rown * KPAD + bkof) * 2;
                ldm_x4(fbh + half * 4, aBh + o);
                ldm_x4(fbl + half * 4, aBl + o);
            }
#pragma unroll
            for (int mt = 0; mt < 4; mt++) {
#pragma unroll
                for (int nt = 0; nt < 4; nt++) {
                    int bi = (nt >> 1) * 4 + (nt & 1) * 2;
                    mma_bf16(acc[mt][nt], fah[mt], fbh[bi], fbh[bi + 1]);
                    mma_bf16(acc[mt][nt], fah[mt], fbl[bi], fbl[bi + 1]);
                    mma_bf16(acc[mt][nt], fal[mt], fbh[bi], fbh[bi + 1]);
                }
            }
        }
        __syncthreads();
    }

    PDL_TRIGGER();   // mainloop done; successor may launch

#pragma unroll
    for (int mt = 0; mt < 4; mt++) {
#pragma unroll
        for (int nt = 0; nt < 4; nt++) {
            int col = col0 + wn * 32 + nt * 8 + 2 * (lane & 3);
            float bx = 0.f, by = 0.f;
            if (bias) { bx = bias[col]; by = bias[col + 1]; }
#pragma unroll
            for (int h = 0; h < 2; h++) {
                int row = row0 + wm * 64 + mt * 16 + (lane >> 2) + h * 8;
                if (row < M) {
                    float vx = acc[mt][nt][2 * h] + bx;
                    float vy = acc[mt][nt][2 * h + 1] + by;
                    if (do_relu) { vx = fmaxf(vx, 0.f); vy = fmaxf(vy, 0.f); }
                    if (ohi) {
                        __nv_bfloat16 hx = __float2bfloat16(vx);
                        __nv_bfloat16 hy = __float2bfloat16(vy);
                        __nv_bfloat162 hh; hh.x = hx; hh.y = hy;
                        __nv_bfloat162 ll;
                        ll.x = __float2bfloat16(vx - __bfloat162float(hx));
                        ll.y = __float2bfloat16(vy - __bfloat162float(hy));
                        *(__nv_bfloat162*)&ohi[(size_t)row * F + col] = hh;
                        *(__nv_bfloat162*)&olo[(size_t)row * F + col] = ll;
                    } else {
                        float2 v; v.x = vx; v.y = vy;
                        *(float2*)&C[(size_t)row * F + col] = v;
                    }
                }
            }
        }
    }
}

// ===========================================================================
// fp32 SGEMM (L1: K=35 odd; L6: F=16 narrow). PDL-instrumented.
// ===========================================================================
#define BM 64
#define BNS 64
#define BK 16

__global__ __launch_bounds__(256) void k_sgemm(
    const float* __restrict__ A, const float* __restrict__ B,
    float* __restrict__ C, int M, int K, int F,
    const float* __restrict__ bias, int do_relu)
{
    __shared__ float As[BK][BM];
    __shared__ float Bs[BK][BNS];

    int tid = threadIdx.x;
    int tx = tid & 15;
    int ty = tid >> 4;
    int row0 = blockIdx.y * BM;
    int col0 = blockIdx.x * BNS;

    float acc[4][4];
#pragma unroll
    for (int i = 0; i < 4; i++)
#pragma unroll
        for (int j = 0; j < 4; j++) acc[i][j] = 0.0f;

    PDL_WAIT();

    for (int k0 = 0; k0 < K; k0 += BK) {
#pragma unroll
        for (int l = 0; l < 4; l++) {
            int e = tid + l * 256;
            int kk = e / BM, mm = e % BM;
            int gr = row0 + mm, gk = k0 + kk;
            As[kk][mm] = (gr < M && gk < K) ? A[(size_t)gr * K + gk] : 0.0f;
            int kk2 = e / BNS, nn = e % BNS;
            int gk2 = k0 + kk2, gc = col0 + nn;
            Bs[kk2][nn] = (gk2 < K && gc < F) ? B[(size_t)gk2 * F + gc] : 0.0f;
        }
        __syncthreads();

#pragma unroll
        for (int kk = 0; kk < BK; kk++) {
            float a[4], b[4];
#pragma unroll
            for (int i = 0; i < 4; i++) a[i] = As[kk][ty * 4 + i];
#pragma unroll
            for (int j = 0; j < 4; j++) b[j] = Bs[kk][tx * 4 + j];
#pragma unroll
            for (int i = 0; i < 4; i++)
#pragma unroll
                for (int j = 0; j < 4; j++) acc[i][j] += a[i] * b[j];
        }
        __syncthreads();
    }

    PDL_TRIGGER();

#pragma unroll
    for (int i = 0; i < 4; i++) {
        int gr = row0 + ty * 4 + i;
        if (gr >= M) continue;
#pragma unroll
        for (int j = 0; j < 4; j++) {
            int gc = col0 + tx * 4 + j;
            if (gc >= F) continue;
            float v = acc[i][j];
            if (bias) v += bias[gc];
            if (do_relu) v = fmaxf(v, 0.0f);
            C[(size_t)gr * F + gc] = v;
        }
    }
}

// ===========================================================================
// Host orchestration
// ===========================================================================
static inline int st_bytes(int BN) { return 2 * 128 * KPAD * 2 + 2 * BN * KPAD * 2; }

// PDL launch helper: programmatic stream serialization on the capture stream.
static inline void launch_pdl(const void* func, dim3 grid, dim3 block,
                              size_t smem, void** args) {
    cudaLaunchConfig_t cfg = {};
    cfg.gridDim = grid;
    cfg.blockDim = block;
    cfg.dynamicSmemBytes = smem;
    cfg.stream = 0;
    cudaLaunchAttribute attr[1];
    attr[0].id = cudaLaunchAttributeProgrammaticStreamSerialization;
    attr[0].val.programmaticStreamSerializationAllowed = 1;
    cfg.attrs = attr;
    cfg.numAttrs = 1;
    cudaLaunchKernelExC(&cfg, func, args);
}

static inline void launch_mma(const __nv_bfloat16* Ah, const __nv_bfloat16* Al,
                              const __nv_bfloat16* Bh, const __nv_bfloat16* Bl,
                              float* C, __nv_bfloat16* ohi, __nv_bfloat16* olo,
                              int K, int F, const float* bias, int relu) {
    int M = NN;
    void* args[] = { &Ah, &Al, &Bh, &Bl, &C, &ohi, &olo, &M, &K, &F, &bias, &relu };
    if (F % 128 == 0) {
        dim3 g(F / 128, (NN + 127) / 128);
        launch_pdl((const void*)k_mma_gemm<128>, g, dim3(256), 2 * st_bytes(128), args);
    } else {
        dim3 g(F / 64, (NN + 127) / 128);
        launch_pdl((const void*)k_mma_gemm<64>, g, dim3(128), 2 * st_bytes(64), args);
    }
}

static inline void launch_agg(const float* xin, float* out, int F,
                              const float* bias, int relu,
                              __nv_bfloat16* ohi, __nv_bfloat16* olo) {
    int F4 = F / 4;
    long total = (long)NN * F4;
    const float4* xin4 = (const float4*)xin;
    float4* out4 = (float4*)out;
    void* args[] = { &xin4, &out4, &bias, &F4, &relu, &ohi, &olo };
    launch_pdl((const void*)k_agg, dim3((unsigned)((total + 255) / 256)), dim3(256), 0, args);
}

static inline void launch_sgemm(const float* A, const float* B, float* C,
                                int K, int F, const float* bias, int relu) {
    int M = NN;
    void* args[] = { &A, &B, &C, &M, &K, &F, &bias, &relu };
    dim3 g((F + BNS - 1) / BNS, (NN + BM - 1) / BM);
    launch_pdl((const void*)k_sgemm, g, dim3(256), 0, args);
}

extern "C" void kernel_launch(void* const* d_in, const int* in_sizes, int n_in,
                              void* d_out, int out_size)
{
    const float* x  = (const float*)d_in[0];
    const int*   ei = (const int*)d_in[1];   // [2, E]: row0 = src, row1 = dst
    const int* src = ei;
    const int* dst = ei + EE;

    const float* W[6];
    const float* b[6];
    for (int i = 0; i < 6; i++) {
        W[i] = (const float*)d_in[2 + 2 * i];
        b[i] = (const float*)d_in[3 + 2 * i];
    }

    float *X, *H;
    __nv_bfloat16 *Ahi, *Alo, *Bhi, *Blo;
    __nv_bfloat16 *WT2h, *WT2l, *WT3h, *WT3l, *WT4h, *WT4l, *WT5h, *WT5l;
    int* cntp;
    cudaGetSymbolAddress((void**)&X, g_X);
    cudaGetSymbolAddress((void**)&H, g_H);
    cudaGetSymbolAddress((void**)&Ahi, g_Ahi);
    cudaGetSymbolAddress((void**)&Alo, g_Alo);
    cudaGetSymbolAddress((void**)&Bhi, g_Bhi);
    cudaGetSymbolAddress((void**)&Blo, g_Blo);
    cudaGetSymbolAddress((void**)&WT2h, g_WT2h);
    cudaGetSymbolAddress((void**)&WT2l, g_WT2l);
    cudaGetSymbolAddress((void**)&WT3h, g_WT3h);
    cudaGetSymbolAddress((void**)&WT3l, g_WT3l);
    cudaGetSymbolAddress((void**)&WT4h, g_WT4h);
    cudaGetSymbolAddress((void**)&WT4l, g_WT4l);
    cudaGetSymbolAddress((void**)&WT5h, g_WT5h);
    cudaGetSymbolAddress((void**)&WT5l, g_WT5l);
    cudaGetSymbolAddress((void**)&cntp, g_cnt);

    cudaFuncSetAttribute(k_mma_gemm<64>,
                         cudaFuncAttributeMaxDynamicSharedMemorySize, 2 * st_bytes(64));
    cudaFuncSetAttribute(k_mma_gemm<128>,
                         cudaFuncAttributeMaxDynamicSharedMemorySize, 2 * st_bytes(128));

    // Fork the preexisting side streams off the capture stream.
    cudaEventRecord(g_ss.evRoot, 0);
    cudaStreamWaitEvent(g_ss.sCsr, g_ss.evRoot, 0);
    cudaStreamWaitEvent(g_ss.sW,   g_ss.evRoot, 0);

    // --- side stream A: CSR + norm build ---
    cudaMemsetAsync(cntp, 0, NN * sizeof(int), g_ss.sCsr);
    k_count<<<(EE + 255) / 256, 256, 0, g_ss.sCsr>>>(dst);
    k_scan<<<1, 1024, 0, g_ss.sCsr>>>();
    k_fill<<<(EE + 255) / 256, 256, 0, g_ss.sCsr>>>(src, dst);
    cudaEventRecord(g_ss.evCsr, g_ss.sCsr);

    // --- side stream B: all weight converts (into dedicated buffers) ---
    k_convW<<<(64 * 256 + 255) / 256, 256, 0, g_ss.sW>>>(W[1], WT2h, WT2l, 64, 256);
    k_convW<<<(256 * 512 + 255) / 256, 256, 0, g_ss.sW>>>(W[2], WT3h, WT3l, 256, 512);
    k_convW<<<(512 * 256 + 255) / 256, 256, 0, g_ss.sW>>>(W[3], WT4h, WT4l, 512, 256);
    k_convW<<<(256 * 64 + 255) / 256, 256, 0, g_ss.sW>>>(W[4], WT5h, WT5l, 256, 64);
    cudaEventRecord(g_ss.evW, g_ss.sW);

    // --- main stream (all PDL-launched) ---
    // L1: 35 -> 64 (fp32 gemm; overlaps with CSR build on sCsr)
    launch_sgemm(x, W[0], H, 35, 64, nullptr, 0);
    cudaStreamWaitEvent(0, g_ss.evCsr, 0);     // join CSR before first agg
    launch_agg(H, X, 64, b[0], 1, nullptr, nullptr);

    // L2: 64 -> 256 (agg-first; agg emits bf16 hi/lo)
    launch_agg(X, nullptr, 64, nullptr, 0, Ahi, Alo);
    cudaStreamWaitEvent(0, g_ss.evW, 0);       // join weight converts
    launch_mma(Ahi, Alo, WT2h, WT2l, X, nullptr, nullptr, 64, 256, b[1], 1);

    // L3: 256 -> 512 (agg-first); MMA epilogue emits hi/lo for L4's GEMM
    launch_agg(X, nullptr, 256, nullptr, 0, Ahi, Alo);
    launch_mma(Ahi, Alo, WT3h, WT3l, nullptr, Bhi, Blo, 256, 512, b[2], 1);

    // L4: 512 -> 256 (gemm-first); agg emits hi/lo for L5's GEMM
    launch_mma(Bhi, Blo, WT4h, WT4l, H, nullptr, nullptr, 512, 256, nullptr, 0);
    launch_agg(H, nullptr, 256, b[3], 1, Ahi, Alo);

    // L5: 256 -> 64; agg writes fp32 X for L6
    launch_mma(Ahi, Alo, WT5h, WT5l, H, nullptr, nullptr, 256, 64, nullptr, 0);
    launch_agg(H, X, 64, b[4], 1, nullptr, nullptr);

    // L6: 64 -> 16 (fp32): gemm without bias, agg adds bias, no relu
    launch_sgemm(X, W[5], H, 64, 16, nullptr, 0);
    launch_agg(H, (float*)d_out, 16, b[5], 0, nullptr, nullptr);
}

// round 15
// speedup vs baseline: 1.0704x; 1.0704x over previous
#include <cuda_runtime.h>
#include <cuda_bf16.h>
#include <cstdint>

#define NN 50000
#define EE 800000
#define FMAX 512
#define NPAD 128   // extra rows: unpredicated cp.async of last row-block stays in-bounds

// Scratch (static device globals — allocation-free)
__device__ float g_X[(size_t)NN * FMAX];   // ping
__device__ float g_H[(size_t)NN * FMAX];   // pong
__device__ __nv_bfloat16 g_Ahi[(size_t)(NN + NPAD) * FMAX];
__device__ __nv_bfloat16 g_Alo[(size_t)(NN + NPAD) * FMAX];
__device__ __nv_bfloat16 g_Bhi[(size_t)(NN + NPAD) * FMAX];
__device__ __nv_bfloat16 g_Blo[(size_t)(NN + NPAD) * FMAX];
// per-layer transposed weight hi/lo
__device__ __nv_bfloat16 g_WT2h[64 * 256],  g_WT2l[64 * 256];
__device__ __nv_bfloat16 g_WT3h[256 * 512], g_WT3l[256 * 512];
__device__ __nv_bfloat16 g_WT4h[512 * 256], g_WT4l[512 * 256];
__device__ __nv_bfloat16 g_WT5h[256 * 64],  g_WT5l[256 * 64];
__device__ float g_dinv[NN];
__device__ int   g_cnt[NN];
__device__ int   g_rowptr[NN + 1];
__device__ int   g_cursor[NN];
__device__ int2  g_csr[EE];     // {src, __float_as_int(norm)}

// ---------------------------------------------------------------------------
// Host-side streams/events, created ONCE at program load (before the harness
// pre-capture memory baseline). kernel_launch creates/destroys nothing.
// ---------------------------------------------------------------------------
struct SideStreams {
    cudaStream_t sCsr = nullptr, sW = nullptr;
    cudaEvent_t evRoot = nullptr, evCsr = nullptr, evW = nullptr;
    SideStreams() {
        cudaStreamCreate(&sCsr);
        cudaStreamCreate(&sW);
        cudaEventCreateWithFlags(&evRoot, cudaEventDisableTiming);
        cudaEventCreateWithFlags(&evCsr,  cudaEventDisableTiming);
        cudaEventCreateWithFlags(&evW,    cudaEventDisableTiming);
        cudaEventRecord(evRoot, sCsr);
        cudaStreamWaitEvent(sW, evRoot, 0);
        cudaStreamSynchronize(sCsr);
        cudaStreamSynchronize(sW);
    }
};
static SideStreams g_ss;

__device__ __forceinline__ uint32_t smem_u32(const void* p) {
    uint32_t a;
    asm("{ .reg .u64 t; cvta.to.shared.u64 t, %1; cvt.u32.u64 %0, t; }"
        : "=r"(a) : "l"(p));
    return a;
}

#define CP_ASYNC16(dst, src) \
    asm volatile("cp.async.cg.shared.global [%0], [%1], 16;" \
                 :: "r"(dst), "l"(src) : "memory")
#define CP_COMMIT() asm volatile("cp.async.commit_group;" ::: "memory")
#define CP_WAIT1()  asm volatile("cp.async.wait_group 1;" ::: "memory")
#define CP_WAIT0()  asm volatile("cp.async.wait_group 0;" ::: "memory")

// ===========================================================================
// CSR build + normalization
// ===========================================================================
__global__ void k_count(const int* __restrict__ dst) {
    int e = blockIdx.x * blockDim.x + threadIdx.x;
    if (e < EE) atomicAdd(&g_cnt[dst[e]], 1);
}

__global__ __launch_bounds__(1024) void k_scan() {
    __shared__ int sh[1024];
    int tid = threadIdx.x;
    const int chunk = (NN + 1023) / 1024;
    int base = tid * chunk;
    int sum = 0;
    for (int i = 0; i < chunk; i++) {
        int idx = base + i;
        if (idx < NN) sum += g_cnt[idx];
    }
    sh[tid] = sum;
    __syncthreads();
    for (int off = 1; off < 1024; off <<= 1) {
        int v = 0;
        if (tid >= off) v = sh[tid - off];
        __syncthreads();
        sh[tid] += v;
        __syncthreads();
    }
    int run = (tid > 0) ? sh[tid - 1] : 0;
    for (int i = 0; i < chunk; i++) {
        int idx = base + i;
        if (idx < NN) {
            g_rowptr[idx] = run;
            g_cursor[idx] = run;
            int c = g_cnt[idx];
            g_dinv[idx] = rsqrtf((float)(c + 1));
            run += c;
        }
    }
    if (tid == 0) g_rowptr[NN] = EE;
}

__global__ void k_fill(const int* __restrict__ src, const int* __restrict__ dst) {
    int e = blockIdx.x * blockDim.x + threadIdx.x;
    if (e < EE) {
        int s = src[e], d = dst[e];
        int pos = atomicAdd(&g_cursor[d], 1);
        int2 p;
        p.x = s;
        p.y = __float_as_int(g_dinv[s] * g_dinv[d]);
        g_csr[pos] = p;
    }
}

// ===========================================================================
// W[K][F] fp32 -> WT[F][K] bf16 hi/lo (transposed)
// ===========================================================================
__global__ void k_convW(const float* __restrict__ W,
                        __nv_bfloat16* __restrict__ WThi,
                        __nv_bfloat16* __restrict__ WTlo, int K, int F)
{
    int i = blockIdx.x * blockDim.x + threadIdx.x;
    if (i >= K * F) return;
    int k = i / F, f = i % F;
    float v = W[i];
    __nv_bfloat16 h = __float2bfloat16(v);
    WThi[(size_t)f * K + k] = h;
    WTlo[(size_t)f * K + k] = __float2bfloat16(v - __bfloat162float(h));
}

// ===========================================================================
// CSR aggregation (gather, no atomics); one float4 column per thread;
// packed int2 csr entries. Optional fp32 out and/or bf16 hi/lo split out.
// ===========================================================================
__global__ __launch_bounds__(256) void k_agg(
    const float4* __restrict__ xin4, float4* __restrict__ out4,
    const float* __restrict__ bias, int F4, int do_relu,
    __nv_bfloat16* __restrict__ ohi, __nv_bfloat16* __restrict__ olo)
{
    long t = (long)blockIdx.x * blockDim.x + threadIdx.x;
    long total = (long)NN * F4;
    if (t >= total) return;
    int n = (int)(t / F4);
    int c = (int)(t % F4);

    float d = g_dinv[n];
    float w0 = d * d;
    float4 x = xin4[(size_t)n * F4 + c];
    float4 acc = make_float4(x.x * w0, x.y * w0, x.z * w0, x.w * w0);

    int s = g_rowptr[n];
    int e = g_rowptr[n + 1];
    for (int j = s; j < e; j++) {
        int2 p = g_csr[j];
        float w = __int_as_float(p.y);
        float4 v = xin4[(size_t)p.x * F4 + c];
        acc.x += w * v.x;
        acc.y += w * v.y;
        acc.z += w * v.z;
        acc.w += w * v.w;
    }
    if (bias) {
        const float4 bv = ((const float4*)bias)[c];
        acc.x += bv.x; acc.y += bv.y; acc.z += bv.z; acc.w += bv.w;
    }
    if (do_relu) {
        acc.x = fmaxf(acc.x, 0.0f);
        acc.y = fmaxf(acc.y, 0.0f);
        acc.z = fmaxf(acc.z, 0.0f);
        acc.w = fmaxf(acc.w, 0.0f);
    }
    if (out4) out4[(size_t)n * F4 + c] = acc;
    if (ohi) {
        size_t base = (size_t)n * (F4 * 4) + (size_t)c * 4;
        float v[4] = {acc.x, acc.y, acc.z, acc.w};
#pragma unroll
        for (int q = 0; q < 2; q++) {
            __nv_bfloat16 h0 = __float2bfloat16(v[2 * q]);
            __nv_bfloat16 h1 = __float2bfloat16(v[2 * q + 1]);
            __nv_bfloat162 hh; hh.x = h0; hh.y = h1;
            __nv_bfloat162 ll;
            ll.x = __float2bfloat16(v[2 * q] - __bfloat162float(h0));
            ll.y = __float2bfloat16(v[2 * q + 1] - __bfloat162float(h1));
            *(__nv_bfloat162*)&ohi[base + 2 * q] = hh;
            *(__nv_bfloat162*)&olo[base + 2 * q] = ll;
        }
    }
}

// ===========================================================================
// Pipelined mma.sync bf16 3-split GEMM (2-stage double buffer).
// Requires K % 32 == 0. CTA tile 128 x BN, threads 2*BN, warp tile 64x32.
// D = Ah*Bh + Ah*Bl + Al*Bh (fp32 accum).
// Epilogue: fp32 C OR bf16 hi/lo split (bias/relu fused).
// ===========================================================================
#define KPAD 40   // smem row stride in bf16 (80B)

__device__ __forceinline__ void ldm_x4(uint32_t* r, uint32_t addr) {
    asm volatile("ldmatrix.sync.aligned.m8n8.x4.shared.b16 {%0,%1,%2,%3}, [%4];"
                 : "=r"(r[0]), "=r"(r[1]), "=r"(r[2]), "=r"(r[3]) : "r"(addr));
}

__device__ __forceinline__ void mma_bf16(float* c, const uint32_t* a,
                                         uint32_t b0, uint32_t b1) {
    asm volatile(
        "mma.sync.aligned.m16n8k16.row.col.f32.bf16.bf16.f32 "
        "{%0,%1,%2,%3}, {%4,%5,%6,%7}, {%8,%9}, {%0,%1,%2,%3};"
        : "+f"(c[0]), "+f"(c[1]), "+f"(c[2]), "+f"(c[3])
        : "r"(a[0]), "r"(a[1]), "r"(a[2]), "r"(a[3]), "r"(b0), "r"(b1));
}

template<int BN>
__device__ __forceinline__ void load_stage(
    uint32_t sbase, const __nv_bfloat16* Ah, const __nv_bfloat16* Al,
    const __nv_bfloat16* Bh, const __nv_bfloat16* Bl,
    int tid, int row0, int col0, int K, int k0)
{
    constexpr int NT = 2 * BN;
    constexpr int ST_AH = 0;
    constexpr int ST_AL = 128 * KPAD * 2;
    constexpr int ST_BH = 2 * 128 * KPAD * 2;
    constexpr int ST_BL = ST_BH + BN * KPAD * 2;

#pragma unroll
    for (int idx = tid; idx < 128 * 4; idx += NT) {
        int r = idx >> 2, q = idx & 3;
        size_t g = (size_t)(row0 + r) * K + k0 + q * 8;
        uint32_t so = (uint32_t)(r * (KPAD * 2) + q * 16);
        CP_ASYNC16(sbase + ST_AH + so, Ah + g);
        CP_ASYNC16(sbase + ST_AL + so, Al + g);
    }
#pragma unroll
    for (int idx = tid; idx < BN * 4; idx += NT) {
        int r = idx >> 2, q = idx & 3;
        size_t g = (size_t)(col0 + r) * K + k0 + q * 8;
        uint32_t so = (uint32_t)(r * (KPAD * 2) + q * 16);
        CP_ASYNC16(sbase + ST_BH + so, Bh + g);
        CP_ASYNC16(sbase + ST_BL + so, Bl + g);
    }
}

template<int BN>
__global__ __launch_bounds__(2 * BN) void k_mma_gemm(
    const __nv_bfloat16* __restrict__ Ah, const __nv_bfloat16* __restrict__ Al,
    const __nv_bfloat16* __restrict__ Bh, const __nv_bfloat16* __restrict__ Bl,
    float* __restrict__ C,
    __nv_bfloat16* __restrict__ ohi, __nv_bfloat16* __restrict__ olo,
    int M, int K, int F,
    const float* __restrict__ bias, int do_relu)
{
    constexpr int ST_AH = 0;
    constexpr int ST_AL = 128 * KPAD * 2;
    constexpr int ST_BH = 2 * 128 * KPAD * 2;
    constexpr int ST_BL = ST_BH + BN * KPAD * 2;
    constexpr int ST_BYTES = ST_BH + 2 * BN * KPAD * 2;

    extern __shared__ char smem[];
    const uint32_t sb = smem_u32(smem);
    const int tid  = threadIdx.x;
    const int lane = tid & 31;
    const int warp = tid >> 5;
    const int wm = warp & 1;
    const int wn = warp >> 1;
    const int row0 = blockIdx.y * 128;
    const int col0 = blockIdx.x * BN;

    float acc[4][4][4];
#pragma unroll
    for (int i = 0; i < 4; i++)
#pragma unroll
        for (int j = 0; j < 4; j++)
#pragma unroll
            for (int q = 0; q < 4; q++) acc[i][j][q] = 0.0f;

    const int nch = K / 32;

    load_stage<BN>(sb, Ah, Al, Bh, Bl, tid, row0, col0, K, 0);
    CP_COMMIT();

    for (int ch = 0; ch < nch; ch++) {
        if (ch + 1 < nch) {
            load_stage<BN>(sb + ((ch + 1) & 1) * ST_BYTES, Ah, Al, Bh, Bl,
                           tid, row0, col0, K, (ch + 1) * 32);
            CP_COMMIT();
            CP_WAIT1();
        } else {
            CP_WAIT0();
        }
        __syncthreads();

        const uint32_t st = sb + (ch & 1) * ST_BYTES;
        const uint32_t aAh = st + ST_AH;
        const uint32_t aAl = st + ST_AL;
        const uint32_t aBh = st + ST_BH;
        const uint32_t aBl = st + ST_BL;

#pragma unroll
        for (int ks = 0; ks < 32; ks += 16) {
            uint32_t fah[4][4], fal[4][4];
            const int qa = lane >> 3;
            const int arow_off = (lane & 7) + (qa & 1) * 8;
            const int akof = ks + (qa >> 1) * 8;
#pragma unroll
            for (int mt = 0; mt < 4; mt++) {
                int row = wm * 64 + mt * 16 + arow_off;
                uint32_t o = (uint32_t)(row * KPAD + akof) * 2;
                ldm_x4(fah[mt], aAh + o);
                ldm_x4(fal[mt], aAl + o);
            }
            uint32_t fbh[8], fbl[8];
            const int qb = lane >> 3;
            const int brow_base = (lane & 7) + (qb >> 1) * 8;
            const int bkof = ks + (qb & 1) * 8;
#pragma unroll
            for (int half = 0; half < 2; half++) {
                int rown = wn * 32 + half * 16 + brow_base;
                uint32_t o = (uint32_t)(rown * KPAD + bkof) * 2;
                ldm_x4(fbh + half * 4, aBh + o);
                ldm_x4(fbl + half * 4, aBl + o);
            }
#pragma unroll
            for (int mt = 0; mt < 4; mt++) {
#pragma unroll
                for (int nt = 0; nt < 4; nt++) {
                    int bi = (nt >> 1) * 4 + (nt & 1) * 2;
                    mma_bf16(acc[mt][nt], fah[mt], fbh[bi], fbh[bi + 1]);
                    mma_bf16(acc[mt][nt], fah[mt], fbl[bi], fbl[bi + 1]);
                    mma_bf16(acc[mt][nt], fal[mt], fbh[bi], fbh[bi + 1]);
                }
            }
        }
        __syncthreads();
    }

#pragma unroll
    for (int mt = 0; mt < 4; mt++) {
#pragma unroll
        for (int nt = 0; nt < 4; nt++) {
            int col = col0 + wn * 32 + nt * 8 + 2 * (lane & 3);
            float bx = 0.f, by = 0.f;
            if (bias) { bx = bias[col]; by = bias[col + 1]; }
#pragma unroll
            for (int h = 0; h < 2; h++) {
                int row = row0 + wm * 64 + mt * 16 + (lane >> 2) + h * 8;
                if (row < M) {
                    float vx = acc[mt][nt][2 * h] + bx;
                    float vy = acc[mt][nt][2 * h + 1] + by;
                    if (do_relu) { vx = fmaxf(vx, 0.f); vy = fmaxf(vy, 0.f); }
                    if (ohi) {
                        __nv_bfloat16 hx = __float2bfloat16(vx);
                        __nv_bfloat16 hy = __float2bfloat16(vy);
                        __nv_bfloat162 hh; hh.x = hx; hh.y = hy;
                        __nv_bfloat162 ll;
                        ll.x = __float2bfloat16(vx - __bfloat162float(hx));
                        ll.y = __float2bfloat16(vy - __bfloat162float(hy));
                        *(__nv_bfloat162*)&ohi[(size_t)row * F + col] = hh;
                        *(__nv_bfloat162*)&olo[(size_t)row * F + col] = ll;
                    } else {
                        float2 v; v.x = vx; v.y = vy;
                        *(float2*)&C[(size_t)row * F + col] = v;
                    }
                }
            }
        }
    }
}

// ===========================================================================
// fp32 SGEMM (L1: K=35 odd, F=64)
// ===========================================================================
#define BM 64
#define BNS 64
#define BK 16

__global__ __launch_bounds__(256) void k_sgemm(
    const float* __restrict__ A, const float* __restrict__ B,
    float* __restrict__ C, int M, int K, int F,
    const float* __restrict__ bias, int do_relu)
{
    __shared__ float As[BK][BM];
    __shared__ float Bs[BK][BNS];

    int tid = threadIdx.x;
    int tx = tid & 15;
    int ty = tid >> 4;
    int row0 = blockIdx.y * BM;
    int col0 = blockIdx.x * BNS;

    float acc[4][4];
#pragma unroll
    for (int i = 0; i < 4; i++)
#pragma unroll
        for (int j = 0; j < 4; j++) acc[i][j] = 0.0f;

    for (int k0 = 0; k0 < K; k0 += BK) {
#pragma unroll
        for (int l = 0; l < 4; l++) {
            int e = tid + l * 256;
            int kk = e / BM, mm = e % BM;
            int gr = row0 + mm, gk = k0 + kk;
            As[kk][mm] = (gr < M && gk < K) ? A[(size_t)gr * K + gk] : 0.0f;
            int kk2 = e / BNS, nn = e % BNS;
            int gk2 = k0 + kk2, gc = col0 + nn;
            Bs[kk2][nn] = (gk2 < K && gc < F) ? B[(size_t)gk2 * F + gc] : 0.0f;
        }
        __syncthreads();

#pragma unroll
        for (int kk = 0; kk < BK; kk++) {
            float a[4], b[4];
#pragma unroll
            for (int i = 0; i < 4; i++) a[i] = As[kk][ty * 4 + i];
#pragma unroll
            for (int j = 0; j < 4; j++) b[j] = Bs[kk][tx * 4 + j];
#pragma unroll
            for (int i = 0; i < 4; i++)
#pragma unroll
                for (int j = 0; j < 4; j++) acc[i][j] += a[i] * b[j];
        }
        __syncthreads();
    }

#pragma unroll
    for (int i = 0; i < 4; i++) {
        int gr = row0 + ty * 4 + i;
        if (gr >= M) continue;
#pragma unroll
        for (int j = 0; j < 4; j++) {
            int gc = col0 + tx * 4 + j;
            if (gc >= F) continue;
            float v = acc[i][j];
            if (bias) v += bias[gc];
            if (do_relu) v = fmaxf(v, 0.0f);
            C[(size_t)gr * F + gc] = v;
        }
    }
}

// ===========================================================================
// Narrow-N fp32 SGEMM for L6 (F=16): 64 rows x 16 cols per 256-thread block,
// no dead columns. Thread t: col = t&15, row group = t>>4 (4 rows each).
// As/Bs reads are warp-broadcast, conflict-free.
// ===========================================================================
__global__ __launch_bounds__(256) void k_sgemm_n16(
    const float* __restrict__ A, const float* __restrict__ B,
    float* __restrict__ C, int M, int K)
{
    constexpr int FN = 16;
    __shared__ float As[BK][BM];
    __shared__ float Bs[BK][FN];

    int tid = threadIdx.x;
    int col = tid & 15;
    int rg  = tid >> 4;          // 0..15, each owns 4 rows
    int row0 = blockIdx.x * BM;

    float acc[4] = {0.f, 0.f, 0.f, 0.f};

    for (int k0 = 0; k0 < K; k0 += BK) {
        // load A tile: 1024 elems, 4/thread
#pragma unroll
        for (int l = 0; l < 4; l++) {
            int e = tid + l * 256;
            int kk = e >> 6, mm = e & 63;
            int gr = row0 + mm, gk = k0 + kk;
            As[kk][mm] = (gr < M && gk < K) ? A[(size_t)gr * K + gk] : 0.0f;
        }
        // load B tile: 256 elems, 1/thread
        {
            int kk = tid >> 4, nn = tid & 15;
            int gk = k0 + kk;
            Bs[kk][nn] = (gk < K) ? B[(size_t)gk * FN + nn] : 0.0f;
        }
        __syncthreads();

#pragma unroll
        for (int kk = 0; kk < BK; kk++) {
            float b = Bs[kk][col];
#pragma unroll
            for (int i = 0; i < 4; i++)
                acc[i] += As[kk][rg * 4 + i] * b;
        }
        __syncthreads();
    }

#pragma unroll
    for (int i = 0; i < 4; i++) {
        int gr = row0 + rg * 4 + i;
        if (gr < M) C[(size_t)gr * FN + col] = acc[i];
    }
}

// ===========================================================================
// Host orchestration
// ===========================================================================
static inline int st_bytes(int BN) { return 2 * 128 * KPAD * 2 + 2 * BN * KPAD * 2; }

static inline void launch_mma(const __nv_bfloat16* Ah, const __nv_bfloat16* Al,
                              const __nv_bfloat16* Bh, const __nv_bfloat16* Bl,
                              float* C, __nv_bfloat16* ohi, __nv_bfloat16* olo,
                              int K, int F, const float* bias, int relu) {
    if (F % 128 == 0) {
        dim3 g(F / 128, (NN + 127) / 128);
        k_mma_gemm<128><<<g, 256, 2 * st_bytes(128)>>>(
            Ah, Al, Bh, Bl, C, ohi, olo, NN, K, F, bias, relu);
    } else {
        dim3 g(F / 64, (NN + 127) / 128);
        k_mma_gemm<64><<<g, 128, 2 * st_bytes(64)>>>(
            Ah, Al, Bh, Bl, C, ohi, olo, NN, K, F, bias, relu);
    }
}

static inline void launch_agg(const float* xin, float* out, int F,
                              const float* bias, int relu,
                              __nv_bfloat16* ohi, __nv_bfloat16* olo) {
    int F4 = F / 4;
    long total = (long)NN * F4;
    k_agg<<<(int)((total + 255) / 256), 256>>>(
        (const float4*)xin, (float4*)out, bias, F4, relu, ohi, olo);
}

extern "C" void kernel_launch(void* const* d_in, const int* in_sizes, int n_in,
                              void* d_out, int out_size)
{
    const float* x  = (const float*)d_in[0];
    const int*   ei = (const int*)d_in[1];   // [2, E]: row0 = src, row1 = dst
    const int* src = ei;
    const int* dst = ei + EE;

    const float* W[6];
    const float* b[6];
    for (int i = 0; i < 6; i++) {
        W[i] = (const float*)d_in[2 + 2 * i];
        b[i] = (const float*)d_in[3 + 2 * i];
    }

    float *X, *H;
    __nv_bfloat16 *Ahi, *Alo, *Bhi, *Blo;
    __nv_bfloat16 *WT2h, *WT2l, *WT3h, *WT3l, *WT4h, *WT4l, *WT5h, *WT5l;
    int* cntp;
    cudaGetSymbolAddress((void**)&X, g_X);
    cudaGetSymbolAddress((void**)&H, g_H);
    cudaGetSymbolAddress((void**)&Ahi, g_Ahi);
    cudaGetSymbolAddress((void**)&Alo, g_Alo);
    cudaGetSymbolAddress((void**)&Bhi, g_Bhi);
    cudaGetSymbolAddress((void**)&Blo, g_Blo);
    cudaGetSymbolAddress((void**)&WT2h, g_WT2h);
    cudaGetSymbolAddress((void**)&WT2l, g_WT2l);
    cudaGetSymbolAddress((void**)&WT3h, g_WT3h);
    cudaGetSymbolAddress((void**)&WT3l, g_WT3l);
    cudaGetSymbolAddress((void**)&WT4h, g_WT4h);
    cudaGetSymbolAddress((void**)&WT4l, g_WT4l);
    cudaGetSymbolAddress((void**)&WT5h, g_WT5h);
    cudaGetSymbolAddress((void**)&WT5l, g_WT5l);
    cudaGetSymbolAddress((void**)&cntp, g_cnt);

    cudaFuncSetAttribute(k_mma_gemm<64>,
                         cudaFuncAttributeMaxDynamicSharedMemorySize, 2 * st_bytes(64));
    cudaFuncSetAttribute(k_mma_gemm<128>,
                         cudaFuncAttributeMaxDynamicSharedMemorySize, 2 * st_bytes(128));

    // Fork the preexisting side streams off the capture stream.
    cudaEventRecord(g_ss.evRoot, 0);
    cudaStreamWaitEvent(g_ss.sCsr, g_ss.evRoot, 0);
    cudaStreamWaitEvent(g_ss.sW,   g_ss.evRoot, 0);

    // --- side stream A: CSR + norm build ---
    cudaMemsetAsync(cntp, 0, NN * sizeof(int), g_ss.sCsr);
    k_count<<<(EE + 255) / 256, 256, 0, g_ss.sCsr>>>(dst);
    k_scan<<<1, 1024, 0, g_ss.sCsr>>>();
    k_fill<<<(EE + 255) / 256, 256, 0, g_ss.sCsr>>>(src, dst);
    cudaEventRecord(g_ss.evCsr, g_ss.sCsr);

    // --- side stream B: all weight converts (into dedicated buffers) ---
    k_convW<<<(64 * 256 + 255) / 256, 256, 0, g_ss.sW>>>(W[1], WT2h, WT2l, 64, 256);
    k_convW<<<(256 * 512 + 255) / 256, 256, 0, g_ss.sW>>>(W[2], WT3h, WT3l, 256, 512);
    k_convW<<<(512 * 256 + 255) / 256, 256, 0, g_ss.sW>>>(W[3], WT4h, WT4l, 512, 256);
    k_convW<<<(256 * 64 + 255) / 256, 256, 0, g_ss.sW>>>(W[4], WT5h, WT5l, 256, 64);
    cudaEventRecord(g_ss.evW, g_ss.sW);

    // --- main stream ---
    // L1: 35 -> 64 (fp32 gemm; overlaps with CSR build on sCsr)
    {
        dim3 g((64 + BNS - 1) / BNS, (NN + BM - 1) / BM);
        k_sgemm<<<g, 256>>>(x, W[0], H, NN, 35, 64, nullptr, 0);
    }
    cudaStreamWaitEvent(0, g_ss.evCsr, 0);     // join CSR before first agg
    launch_agg(H, X, 64, b[0], 1, nullptr, nullptr);

    // L2: 64 -> 256 (agg-first; agg emits bf16 hi/lo)
    launch_agg(X, nullptr, 64, nullptr, 0, Ahi, Alo);
    cudaStreamWaitEvent(0, g_ss.evW, 0);       // join weight converts
    launch_mma(Ahi, Alo, WT2h, WT2l, X, nullptr, nullptr, 64, 256, b[1], 1);

    // L3: 256 -> 512 (agg-first); MMA epilogue emits hi/lo for L4's GEMM
    launch_agg(X, nullptr, 256, nullptr, 0, Ahi, Alo);
    launch_mma(Ahi, Alo, WT3h, WT3l, nullptr, Bhi, Blo, 256, 512, b[2], 1);

    // L4: 512 -> 256 (gemm-first); agg emits hi/lo for L5's GEMM
    launch_mma(Bhi, Blo, WT4h, WT4l, H, nullptr, nullptr, 512, 256, nullptr, 0);
    launch_agg(H, nullptr, 256, b[3], 1, Ahi, Alo);

    // L5: 256 -> 64; agg writes fp32 X for L6
    launch_mma(Ahi, Alo, WT5h, WT5l, H, nullptr, nullptr, 256, 64, nullptr, 0);
    launch_agg(H, X, 64, b[4], 1, nullptr, nullptr);

    // L6: 64 -> 16 (narrow-N fp32 path): gemm without bias, agg adds bias, no relu
    k_sgemm_n16<<<(NN + BM - 1) / BM, 256>>>(X, W[5], H, NN, 64);
    launch_agg(H, (float*)d_out, 16, b[5], 0, nullptr, nullptr);
}